// round 10
// baseline (speedup 1.0000x reference)
#include <cuda_runtime.h>
#include <cuda_fp16.h>
#include <cstdint>

#define V     8      // output rows per block-tile
#define XPT   4      // output cols per thread (two half2 pairs)
#define RIN   (V + 4)
#define WIMG  1024
#define HIMG  1024
#define SROW  1040   // halfs per smem row (4 pad + 1024 + halo + slack)

__constant__ __half2 c_w2[25];        // packed (w,w) per tap — constant loads, 0 GPRs
__device__   __half2 g_w2_stage[25];  // staging (device-writable scratch)

__global__ void prep_weights(const float* __restrict__ filt)
{
    const int t = threadIdx.x;
    if (t < 25) g_w2_stage[t] = __floats2half2_rn(filt[t], filt[t]);
}

// (hi(a), lo(b)) from two half2's: bytes {a.b2,a.b3,b.b0,b.b1}.
__device__ __forceinline__ __half2 shift_pair(__half2 a, __half2 b)
{
    const uint32_t r = __byte_perm(*reinterpret_cast<uint32_t*>(&a),
                                   *reinterpret_cast<uint32_t*>(&b), 0x5432);
    return *reinterpret_cast<const __half2*>(&r);
}

__global__ __launch_bounds__(256, 6)
void erosion5x5_kernel(const float* __restrict__ img,
                       float* __restrict__ out)
{
    // smem tile: logical col c (-2..1025) lives at half-index c+4 (8B-aligned stores).
    __shared__ __half sbuf[RIN][SROW];

    const int plane = blockIdx.y;                 // fused (b,c): 0..95
    const int y0    = blockIdx.x * V;             // output row base
    const int t     = threadIdx.x;
    const int x0    = t * XPT;                    // 0, 4, ..., 1020

    const float* p = img + (size_t)plane * HIMG * WIMG;
    float*       q = out + (size_t)plane * HIMG * WIMG + (size_t)y0 * WIMG + x0;

    const float   INF  = __int_as_float(0x7f800000);
    const __half2 INF2 = __floats2half2_rn(INF, INF);

    // ---- Phase 1: stage 12 input rows to smem as fp16 (convert once) ----
#pragma unroll
    for (int r = 0; r < RIN; ++r) {
        const int yy = y0 - 2 + r;                // block-uniform bound check
        float4 v;
        if (yy >= 0 && yy < HIMG)
            v = *reinterpret_cast<const float4*>(p + (size_t)yy * WIMG + t * 4);
        else
            v = make_float4(INF, INF, INF, INF);
        __half2* dst = reinterpret_cast<__half2*>(&sbuf[r][4 + t * 4]);
        dst[0] = __floats2half2_rn(v.x, v.y);
        dst[1] = __floats2half2_rn(v.z, v.w);
    }
    // Column halos: cols -2,-1 at idx 2..3, cols 1024,1025 at idx 1028..1029.
    if (t < RIN) {
        *reinterpret_cast<__half2*>(&sbuf[t][2])    = INF2;
    } else if (t >= 32 && t < 32 + RIN) {
        *reinterpret_cast<__half2*>(&sbuf[t - 32][1028]) = INF2;
    }
    __syncthreads();

    // ---- Phase 2: register-streamed erosion from smem ----
    __half2 acc[V][2];
#pragma unroll
    for (int o = 0; o < V; ++o) { acc[o][0] = INF2; acc[o][1] = INF2; }

#pragma unroll
    for (int r = 0; r < RIN; ++r) {
        // 8 halfs: cols x0-2 .. x0+5 -> idx (x0+2)..(x0+9); 4B-aligned half2 loads.
        const __half2* src = reinterpret_cast<const __half2*>(&sbuf[r][2 + x0]);
        __half2 P[7];
        P[0] = src[0];                 // (s0,s1)
        P[2] = src[1];                 // (s2,s3)
        P[4] = src[2];                 // (s4,s5)
        P[6] = src[3];                 // (s6,s7)
        P[1] = shift_pair(P[0], P[2]); // (s1,s2)
        P[3] = shift_pair(P[2], P[4]); // (s3,s4)
        P[5] = shift_pair(P[4], P[6]); // (s5,s6)

        // Input row r feeds output row o = r - i through filter row i.
#pragma unroll
        for (int i = 0; i < 5; ++i) {
            const int o = r - i;
            if (o < 0 || o >= V) continue;   // compile-time pruned
#pragma unroll
            for (int j = 0; j < 5; ++j) {
                const __half2 w = c_w2[i * 5 + j];   // constant load, 0 GPRs
                acc[o][0] = __hmin2(acc[o][0], __hsub2(P[j],     w));   // cols (0,1)
                acc[o][1] = __hmin2(acc[o][1], __hsub2(P[j + 2], w));   // cols (2,3)
            }
        }
    }

#pragma unroll
    for (int o = 0; o < V; ++o) {
        const float2 lo = __half22float2(acc[o][0]);
        const float2 hi = __half22float2(acc[o][1]);
        float4 v = make_float4(lo.x, lo.y, hi.x, hi.y);
        *reinterpret_cast<float4*>(q + (size_t)o * WIMG) = v;   // STG.128
    }
}

extern "C" void kernel_launch(void* const* d_in, const int* in_sizes, int n_in,
                              void* d_out, int out_size)
{
    const float* img  = (const float*)d_in[0];
    const float* filt = (const float*)d_in[1];
    float*       out  = (float*)d_out;

    // 1) Convert filter -> packed half2 in device staging array.
    prep_weights<<<1, 32>>>(filt);

    // 2) Stage -> constant bank (D2D memcpy node; graph-capturable, no alloc).
    void* stage_ptr = nullptr;
    cudaGetSymbolAddress(&stage_ptr, g_w2_stage);
    cudaMemcpyToSymbolAsync(c_w2, stage_ptr, 25 * sizeof(__half2), 0,
                            cudaMemcpyDeviceToDevice, 0);

    const int planes = in_sizes[0] / (HIMG * WIMG);   // 32*3 = 96

    dim3 block(WIMG / XPT);          // 256 threads: one row-strip of the plane
    dim3 grid(HIMG / V, planes);     // (128, 96)
    erosion5x5_kernel<<<grid, block>>>(img, out);
}

// round 11
// speedup vs baseline: 1.3930x; 1.3930x over previous
#include <cuda_runtime.h>
#include <cuda_fp16.h>
#include <cstdint>

#define V    8      // output rows per thread
#define XPT  4      // output cols per thread (two half2 pairs)
#define WIMG 1024
#define HIMG 1024

__constant__ __half2 c_w2[25];        // packed (w,w) per tap — constant loads, 0 GPRs
__device__   __half2 g_w2_stage[25];  // staging (device-writable scratch)

__global__ void prep_weights(const float* __restrict__ filt)
{
    const int t = threadIdx.x;
    if (t < 25) g_w2_stage[t] = __floats2half2_rn(filt[t], filt[t]);
}

// (hi(a), lo(b)) from two half2's: bytes {a.b2,a.b3,b.b0,b.b1}.
__device__ __forceinline__ __half2 shift_pair(__half2 a, __half2 b)
{
    const uint32_t r = __byte_perm(*reinterpret_cast<uint32_t*>(&a),
                                   *reinterpret_cast<uint32_t*>(&b), 0x5432);
    return *reinterpret_cast<const __half2*>(&r);
}

__global__ __launch_bounds__(256, 5)
void erosion5x5_kernel(const float* __restrict__ img,
                       float* __restrict__ out)
{
    const int plane = blockIdx.y;                 // fused (b,c): 0..95
    const int y0    = blockIdx.x * V;             // output row base
    const int x0    = threadIdx.x * XPT;          // 0, 4, ..., 1020

    const float* p = img + (size_t)plane * HIMG * WIMG;
    float*       q = out + (size_t)plane * HIMG * WIMG + (size_t)y0 * WIMG + x0;

    const float   INF  = __int_as_float(0x7f800000);
    const __half2 INF2 = __floats2half2_rn(INF, INF);

    // Accumulators: V rows x 2 column-pairs, fp16x2.
    __half2 acc[V][2];
#pragma unroll
    for (int o = 0; o < V; ++o) { acc[o][0] = INF2; acc[o][1] = INF2; }

    // Thread needs cols x0-2 .. x0+5.
    const bool leftEdge  = (x0 == 0);              // cols x0-2, x0-1 OOB
    const bool rightEdge = (x0 + 4 >= WIMG);       // cols x0+4, x0+5 OOB (only x0==1020)

    // Stream input rows y0-2 .. y0+V+1 through registers.
    // s[k] = img[row][x0 - 2 + k], k = 0..7  (float2 + float4 + float2, all aligned).
#pragma unroll
    for (int r = 0; r < V + 4; ++r) {
        const int yy = y0 - 2 + r;
        __half2 P[7];                    // P[k] = (s[k], s[k+1]), k = 0..6
        if (yy >= 0 && yy < HIMG) {
            const float* row = p + (size_t)yy * WIMG + x0;
            float2 a  = leftEdge  ? make_float2(INF, INF)
                                  : *reinterpret_cast<const float2*>(row - 2);
            float4 b  = *reinterpret_cast<const float4*>(row);
            float2 c2 = rightEdge ? make_float2(INF, INF)
                                  : *reinterpret_cast<const float2*>(row + 4);
            // s = {a.x, a.y, b.x, b.y, b.z, b.w, c2.x, c2.y}
            P[0] = __floats2half2_rn(a.x,  a.y);    // (s0,s1)
            P[2] = __floats2half2_rn(b.x,  b.y);    // (s2,s3)
            P[4] = __floats2half2_rn(b.z,  b.w);    // (s4,s5)
            P[6] = __floats2half2_rn(c2.x, c2.y);   // (s6,s7)
            P[1] = shift_pair(P[0], P[2]);          // (s1,s2) — bitwise = cvt
            P[3] = shift_pair(P[2], P[4]);          // (s3,s4)
            P[5] = shift_pair(P[4], P[6]);          // (s5,s6)
        } else {
#pragma unroll
            for (int k = 0; k < 7; ++k) P[k] = INF2;
        }

        // Input row (rel index r) feeds output row o = r - i through filter row i.
#pragma unroll
        for (int i = 0; i < 5; ++i) {
            const int o = r - i;
            if (o < 0 || o >= V) continue;   // compile-time pruned
#pragma unroll
            for (int j = 0; j < 5; ++j) {
                const __half2 w = c_w2[i * 5 + j];   // constant load, 0 GPRs
                // cols (0,1): taps start at s[j]   -> P[j]
                // cols (2,3): taps start at s[j+2] -> P[j+2]
                acc[o][0] = __hmin2(acc[o][0], __hsub2(P[j],     w));
                acc[o][1] = __hmin2(acc[o][1], __hsub2(P[j + 2], w));
            }
        }
    }

#pragma unroll
    for (int o = 0; o < V; ++o) {
        const float2 lo = __half22float2(acc[o][0]);
        const float2 hi = __half22float2(acc[o][1]);
        float4 v = make_float4(lo.x, lo.y, hi.x, hi.y);
        *reinterpret_cast<float4*>(q + (size_t)o * WIMG) = v;   // STG.128
    }
}

extern "C" void kernel_launch(void* const* d_in, const int* in_sizes, int n_in,
                              void* d_out, int out_size)
{
    const float* img  = (const float*)d_in[0];
    const float* filt = (const float*)d_in[1];
    float*       out  = (float*)d_out;

    // 1) Convert filter -> packed half2 in device staging array.
    prep_weights<<<1, 32>>>(filt);

    // 2) Stage -> constant bank (D2D memcpy node; graph-capturable, no alloc).
    void* stage_ptr = nullptr;
    cudaGetSymbolAddress(&stage_ptr, g_w2_stage);
    cudaMemcpyToSymbolAsync(c_w2, stage_ptr, 25 * sizeof(__half2), 0,
                            cudaMemcpyDeviceToDevice, 0);

    const int planes = in_sizes[0] / (HIMG * WIMG);   // 32*3 = 96

    dim3 block(WIMG / XPT);          // 256 threads: one row-strip of the plane
    dim3 grid(HIMG / V, planes);     // (128, 96)
    erosion5x5_kernel<<<grid, block>>>(img, out);
}

// round 12
// speedup vs baseline: 1.5662x; 1.1243x over previous
#include <cuda_runtime.h>
#include <cuda_fp16.h>
#include <cstdint>

#define V    8      // output rows per thread
#define XPT  4      // output cols per thread (two half2 pairs)
#define RIN  (V + 4)
#define WIMG 1024
#define HIMG 1024

__constant__ __half2 c_w2[25];        // packed (w,w) per tap — constant loads, 0 GPRs
__device__   __half2 g_w2_stage[25];  // staging (device-writable scratch)

__global__ void prep_weights(const float* __restrict__ filt)
{
    const int t = threadIdx.x;
    if (t < 25) g_w2_stage[t] = __floats2half2_rn(filt[t], filt[t]);
}

// (hi(a), lo(b)) from two half2's: bytes {a.b2,a.b3,b.b0,b.b1}.
__device__ __forceinline__ __half2 shift_pair(__half2 a, __half2 b)
{
    const uint32_t r = __byte_perm(*reinterpret_cast<uint32_t*>(&a),
                                   *reinterpret_cast<uint32_t*>(&b), 0x5432);
    return *reinterpret_cast<const __half2*>(&r);
}

__global__ __launch_bounds__(256, 4)
void erosion5x5_kernel(const float* __restrict__ img,
                       float* __restrict__ out)
{
    const int plane = blockIdx.y;                 // fused (b,c): 0..95
    const int y0    = blockIdx.x * V;             // output row base
    const int x0    = threadIdx.x * XPT;          // 0, 4, ..., 1020

    const float* p = img + (size_t)plane * HIMG * WIMG;
    float*       q = out + (size_t)plane * HIMG * WIMG + (size_t)y0 * WIMG + x0;

    const float   INF  = __int_as_float(0x7f800000);
    const __half2 INF2 = __floats2half2_rn(INF, INF);

    // Thread needs cols x0-2 .. x0+5.
    const bool leftEdge  = (x0 == 0);
    const bool rightEdge = (x0 + 4 >= WIMG);      // only x0==1020

    // Row loader: s[k]=img[row][x0-2+k], k=0..7 (float2+float4+float2, aligned).
    auto load_row = [&](int r, float2& a, float4& b, float2& c2) {
        const int yy = y0 - 2 + r;
        if (yy >= 0 && yy < HIMG) {
            const float* row = p + (size_t)yy * WIMG + x0;
            a  = leftEdge  ? make_float2(INF, INF)
                           : *reinterpret_cast<const float2*>(row - 2);
            b  = *reinterpret_cast<const float4*>(row);
            c2 = rightEdge ? make_float2(INF, INF)
                           : *reinterpret_cast<const float2*>(row + 4);
        } else {
            a  = make_float2(INF, INF);
            b  = make_float4(INF, INF, INF, INF);
            c2 = make_float2(INF, INF);
        }
    };

    // Accumulators: V rows x 2 column-pairs, fp16x2.
    __half2 acc[V][2];
#pragma unroll
    for (int o = 0; o < V; ++o) { acc[o][0] = INF2; acc[o][1] = INF2; }

    // Software pipeline: loads for row r+1 issued before row r's math.
    float2 a_cur, c_cur;  float4 b_cur;
    load_row(0, a_cur, b_cur, c_cur);

#pragma unroll
    for (int r = 0; r < RIN; ++r) {
        float2 a_nxt, c_nxt;  float4 b_nxt;
        if (r + 1 < RIN) load_row(r + 1, a_nxt, b_nxt, c_nxt);

        // Pack current row: 4 cvt + 3 PRMT (bitwise = converting each pair).
        __half2 P[7];
        P[0] = __floats2half2_rn(a_cur.x, a_cur.y);   // (s0,s1)
        P[2] = __floats2half2_rn(b_cur.x, b_cur.y);   // (s2,s3)
        P[4] = __floats2half2_rn(b_cur.z, b_cur.w);   // (s4,s5)
        P[6] = __floats2half2_rn(c_cur.x, c_cur.y);   // (s6,s7)
        P[1] = shift_pair(P[0], P[2]);                // (s1,s2)
        P[3] = shift_pair(P[2], P[4]);                // (s3,s4)
        P[5] = shift_pair(P[4], P[6]);                // (s5,s6)

        // Input row r feeds output row o = r - i through filter row i.
#pragma unroll
        for (int i = 0; i < 5; ++i) {
            const int o = r - i;
            if (o < 0 || o >= V) continue;   // compile-time pruned
#pragma unroll
            for (int j = 0; j < 5; ++j) {
                const __half2 w = c_w2[i * 5 + j];   // constant load, 0 GPRs
                acc[o][0] = __hmin2(acc[o][0], __hsub2(P[j],     w));   // cols (0,1)
                acc[o][1] = __hmin2(acc[o][1], __hsub2(P[j + 2], w));   // cols (2,3)
            }
        }

        a_cur = a_nxt;  b_cur = b_nxt;  c_cur = c_nxt;
    }

#pragma unroll
    for (int o = 0; o < V; ++o) {
        const float2 lo = __half22float2(acc[o][0]);
        const float2 hi = __half22float2(acc[o][1]);
        float4 v = make_float4(lo.x, lo.y, hi.x, hi.y);
        *reinterpret_cast<float4*>(q + (size_t)o * WIMG) = v;   // STG.128
    }
}

extern "C" void kernel_launch(void* const* d_in, const int* in_sizes, int n_in,
                              void* d_out, int out_size)
{
    const float* img  = (const float*)d_in[0];
    const float* filt = (const float*)d_in[1];
    float*       out  = (float*)d_out;

    // 1) Convert filter -> packed half2 in device staging array.
    prep_weights<<<1, 32>>>(filt);

    // 2) Stage -> constant bank (D2D memcpy node; graph-capturable, no alloc).
    void* stage_ptr = nullptr;
    cudaGetSymbolAddress(&stage_ptr, g_w2_stage);
    cudaMemcpyToSymbolAsync(c_w2, stage_ptr, 25 * sizeof(__half2), 0,
                            cudaMemcpyDeviceToDevice, 0);

    const int planes = in_sizes[0] / (HIMG * WIMG);   // 32*3 = 96

    dim3 block(WIMG / XPT);          // 256 threads: one row-strip of the plane
    dim3 grid(HIMG / V, planes);     // (128, 96)
    erosion5x5_kernel<<<grid, block>>>(img, out);
}